// round 2
// baseline (speedup 1.0000x reference)
#include <cuda_runtime.h>

// Shapes: re, gt are (B=32, C=10, H=192, W=320) float32, contiguous.
#define NB   32
#define NC   10
#define HW   (192*320)      // 61440
#define HW4  (HW/4)         // 15360
#define N4   (NB*HW4)       // 491520 four-pixel groups
#define NACC 11

// [0]=nv [1]=num_pos [2]=pos_term [3]=neg_term [4]=S_pos
// [5]=S_len1 [6]=S_len2 [7]=S_trig1 [8]=S_trig2 [9]=S_const [10]=S_h
__device__ float g_acc[NACC];

__device__ __forceinline__ float sl1(float d) {
    float ad = fabsf(d);
    return ad < 1.0f ? 0.5f * d * d : ad - 0.5f;
}

__device__ __forceinline__ float c4(const float4& v, int j) {
    return j == 0 ? v.x : (j == 1 ? v.y : (j == 2 ? v.z : v.w));
}

__global__ void zero_kernel() {
    if (threadIdx.x < NACC) g_acc[threadIdx.x] = 0.0f;
}

__global__ void __launch_bounds__(256)
loss_kernel(const float* __restrict__ re, const float* __restrict__ gt) {
    float acc[NACC];
#pragma unroll
    for (int k = 0; k < NACC; k++) acc[k] = 0.0f;

    const float4* __restrict__ re4 = (const float4*)re;
    const float4* __restrict__ gt4 = (const float4*)gt;

    for (int i = blockIdx.x * blockDim.x + threadIdx.x; i < N4;
         i += gridDim.x * blockDim.x) {
        int b   = i / HW4;
        int hw4 = i - b * HW4;
        int base = b * (NC * HW4) + hw4;   // float4-unit index of (b, c=0, hw)

        float4 G0 = gt4[base];
        float4 R0 = re4[base];

        bool mv[4];
        bool any = false;
#pragma unroll
        for (int j = 0; j < 4; j++) {
            float g = c4(G0, j);
            float r = c4(R0, j);
            bool m = (g == 1.0f);
            mv[j] = m;
            any |= m;
            if (m) acc[0] += 1.0f;
            if (g >= 0.0f) {
                float safe = fminf(fmaxf(r, 1e-6f), 1.0f - 1e-6f);
                if (g >= 0.1f) {   // FOCAL_THR
                    acc[1] += 1.0f;
                    float d = g - r;
                    acc[2] -= d * d * logf(safe + 6e-8f);
                } else {
                    float om  = 1.0f - g;
                    float om2 = om * om;
                    acc[3] -= r * r * logf(1.0f + 6e-8f - safe) * om2 * om2;
                }
            }
        }

        if (any) {
            // pos_loss: channels (1,1),(2,2)
            {
                float4 R1 = re4[base + 1 * HW4], G1 = gt4[base + 1 * HW4];
                float4 R2 = re4[base + 2 * HW4], G2 = gt4[base + 2 * HW4];
#pragma unroll
                for (int j = 0; j < 4; j++) if (mv[j]) {
                    acc[4] += sl1(c4(R1, j) - c4(G1, j))
                            + sl1(c4(R2, j) - c4(G2, j));
                }
            }
            // length v1/v2: channels 3 & 6 (straight and crossed)
            {
                float4 R3 = re4[base + 3 * HW4], G3 = gt4[base + 3 * HW4];
                float4 R6 = re4[base + 6 * HW4], G6 = gt4[base + 6 * HW4];
#pragma unroll
                for (int j = 0; j < 4; j++) if (mv[j]) {
                    float r3 = c4(R3, j), g3 = c4(G3, j);
                    float r6 = c4(R6, j), g6 = c4(G6, j);
                    acc[5] += sl1(r3 - g3) + sl1(r6 - g6);
                    acc[6] += sl1(r3 - g6) + sl1(r6 - g3);
                }
            }
            // trig v1/v2 + const: channels 4,5,7,8
            {
                float4 R4 = re4[base + 4 * HW4], G4 = gt4[base + 4 * HW4];
                float4 R5 = re4[base + 5 * HW4], G5 = gt4[base + 5 * HW4];
                float4 R7 = re4[base + 7 * HW4], G7 = gt4[base + 7 * HW4];
                float4 R8 = re4[base + 8 * HW4], G8 = gt4[base + 8 * HW4];
#pragma unroll
                for (int j = 0; j < 4; j++) if (mv[j]) {
                    float r4 = c4(R4, j), g4 = c4(G4, j);
                    float r5 = c4(R5, j), g5 = c4(G5, j);
                    float r7 = c4(R7, j), g7 = c4(G7, j);
                    float r8 = c4(R8, j), g8 = c4(G8, j);
                    float d44 = r4 - g4, d77 = r7 - g7;
                    float d55 = r5 - g5, d88 = r8 - g8;
                    acc[7] += d44 * d44 + d77 * d77 + d55 * d55 + d88 * d88;
                    float d47 = r4 - g7, d74 = r7 - g4;
                    float d58 = r5 - g8, d85 = r8 - g5;
                    acc[8] += d47 * d47 + d74 * d74 + d58 * d58 + d85 * d85;
                    float c1 = 1.0f - r5 * r5 - r4 * r4;
                    float c2 = 1.0f - r8 * r8 - r7 * r7;
                    acc[9] += c1 * c1 + c2 * c2;
                }
            }
            // height: channel 9
            {
                float4 R9 = re4[base + 9 * HW4], G9 = gt4[base + 9 * HW4];
#pragma unroll
                for (int j = 0; j < 4; j++) if (mv[j]) {
                    acc[10] += sl1(c4(R9, j) - c4(G9, j));
                }
            }
        }
    }

    // Block reduction: warp shuffle -> shared -> atomicAdd
    __shared__ float sh[8][NACC];
    int lane = threadIdx.x & 31;
    int warp = threadIdx.x >> 5;
#pragma unroll
    for (int k = 0; k < NACC; k++) {
        float v = acc[k];
#pragma unroll
        for (int o = 16; o > 0; o >>= 1)
            v += __shfl_down_sync(0xffffffffu, v, o);
        if (lane == 0) sh[warp][k] = v;
    }
    __syncthreads();
    if (threadIdx.x < NACC) {
        float v = 0.0f;
#pragma unroll
        for (int w = 0; w < 8; w++) v += sh[w][threadIdx.x];
        atomicAdd(&g_acc[threadIdx.x], v);
    }
}

__global__ void finalize_kernel(float* __restrict__ out) {
    float nv       = g_acc[0];
    float num_pos  = g_acc[1];
    float pos_term = g_acc[2];
    float neg_term = g_acc[3];

    float focal = (num_pos == 0.0f) ? neg_term
                                    : (pos_term + neg_term) / num_pos;
    float inv2nv = 1.0f / (2.0f * nv);
    float invnv  = 1.0f / nv;

    float confidence_loss = 1.0f * focal;                 // CONF_W
    float pos_loss  = 1.0f * g_acc[4] * inv2nv;           // POS_W
    float len_v1    = 0.1f * g_acc[5] * inv2nv;           // LEN_W
    float len_v2    = 0.1f * g_acc[6] * inv2nv;
    float trig_v1   = 1.0f * g_acc[7] * inv2nv;           // TRIG_W
    float trig_v2   = 1.0f * g_acc[8] * inv2nv;
    float const_loss = 0.5f * g_acc[9] * invnv;           // CONST_W
    float height    = 0.1f * g_acc[10] * invnv;           // LEN_W

    float dims = fminf(len_v1 + trig_v1, len_v2 + trig_v2) + height;
    out[0] = confidence_loss + pos_loss + dims + const_loss;
}

extern "C" void kernel_launch(void* const* d_in, const int* in_sizes, int n_in,
                              void* d_out, int out_size) {
    const float* re = (const float*)d_in[0];
    const float* gt = (const float*)d_in[1];
    float* out = (float*)d_out;

    zero_kernel<<<1, 32>>>();
    loss_kernel<<<960, 256>>>(re, gt);
    finalize_kernel<<<1, 1>>>(out);
}